// round 1
// baseline (speedup 1.0000x reference)
#include <cuda_runtime.h>
#include <math.h>

// Problem constants (fixed by dataset)
#define Bq   2
#define Sq   2048
#define Dq   1024
#define Hq   16
#define DKq  64
#define NR   (Bq*Sq)          // 4096 token rows

// Scratch (allocation-free rule: __device__ globals)
__device__ float g_Q [NR*Dq];
__device__ float g_K [NR*Dq];
__device__ float g_V [NR*Dq];
__device__ float g_AO[NR*Dq];

// ---------------------------------------------------------------------------
// GEMM: C[m,n] = sum_k A[m,k] * W[n,k]   (both operands K-contiguous)
// 128x128x8 tile, 256 threads, 8x8 per thread.
// ---------------------------------------------------------------------------
__global__ void __launch_bounds__(256) gemm_nt(const float* __restrict__ A,
                                               const float* __restrict__ W,
                                               float* __restrict__ C,
                                               int M, int N, int K)
{
    __shared__ float As[8][128];
    __shared__ float Bs[8][128];

    const int tid = threadIdx.x;
    const int bm  = blockIdx.y * 128;
    const int bn  = blockIdx.x * 128;

    const int lrow = tid >> 1;          // 0..127
    const int lcol = (tid & 1) * 4;     // 0 or 4

    const float* Ap = A + (size_t)(bm + lrow) * K + lcol;
    const float* Wp = W + (size_t)(bn + lrow) * K + lcol;

    const int tm = (tid >> 4) * 8;
    const int tn = (tid & 15) * 8;

    float acc[8][8];
#pragma unroll
    for (int i = 0; i < 8; i++)
#pragma unroll
        for (int j = 0; j < 8; j++) acc[i][j] = 0.f;

    for (int k0 = 0; k0 < K; k0 += 8) {
        float4 av = *(const float4*)(Ap + k0);
        float4 bv = *(const float4*)(Wp + k0);
        As[lcol + 0][lrow] = av.x; As[lcol + 1][lrow] = av.y;
        As[lcol + 2][lrow] = av.z; As[lcol + 3][lrow] = av.w;
        Bs[lcol + 0][lrow] = bv.x; Bs[lcol + 1][lrow] = bv.y;
        Bs[lcol + 2][lrow] = bv.z; Bs[lcol + 3][lrow] = bv.w;
        __syncthreads();

#pragma unroll
        for (int kk = 0; kk < 8; kk++) {
            float ar[8], br[8];
#pragma unroll
            for (int i = 0; i < 8; i++) ar[i] = As[kk][tm + i];
#pragma unroll
            for (int j = 0; j < 8; j++) br[j] = Bs[kk][tn + j];
#pragma unroll
            for (int i = 0; i < 8; i++)
#pragma unroll
                for (int j = 0; j < 8; j++)
                    acc[i][j] += ar[i] * br[j];
        }
        __syncthreads();
    }

#pragma unroll
    for (int i = 0; i < 8; i++) {
        float4* cp = (float4*)(C + (size_t)(bm + tm + i) * N + bn + tn);
        cp[0] = make_float4(acc[i][0], acc[i][1], acc[i][2], acc[i][3]);
        cp[1] = make_float4(acc[i][4], acc[i][5], acc[i][6], acc[i][7]);
    }
}

// ---------------------------------------------------------------------------
// Fused RMSNorm (over full D=1024) + RoPE (per head of 64) applied in place.
// One block per token row; 256 threads, one float4 per thread.
// ---------------------------------------------------------------------------
__global__ void __launch_bounds__(256) norm_rope_kernel(float* __restrict__ T,
                                                        const float* __restrict__ gain)
{
    const int n = blockIdx.x;
    const int s = n % Sq;                 // position (positions == arange(S))
    float* row = T + (size_t)n * Dq;
    const int t = threadIdx.x;

    float4 x = ((float4*)row)[t];
    float ss = x.x * x.x + x.y * x.y + x.z * x.z + x.w * x.w;
#pragma unroll
    for (int o = 16; o > 0; o >>= 1) ss += __shfl_xor_sync(0xffffffffu, ss, o);

    __shared__ float wsum[8];
    if ((t & 31) == 0) wsum[t >> 5] = ss;
    __syncthreads();
    float tot = 0.f;
#pragma unroll
    for (int i = 0; i < 8; i++) tot += wsum[i];

    const float rinv = rsqrtf(tot * (1.0f / 1024.0f) + 1e-5f);
    const float4 g = ((const float4*)gain)[t];

    // RoPE: dims 4t..4t+3; within-head offset dk = (4t)%64; pairs p0, p0+1.
    const int dk = (t * 4) & 63;
    const int p0 = dk >> 1;
    const double LT_OVER_32 = 9.210340371976184 / 32.0;   // log(10000)/32
    const double f0 = exp(-(double)p0 * LT_OVER_32);
    const double f1 = exp(-(double)(p0 + 1) * LT_OVER_32);
    const float a0 = (float)((double)s * f0);
    const float a1 = (float)((double)s * f1);
    float s0, c0, s1, c1;
    sincosf(a0, &s0, &c0);
    sincosf(a1, &s1, &c1);

    const float e0 = x.x * rinv * g.x, o0 = x.y * rinv * g.y;
    const float e1 = x.z * rinv * g.z, o1 = x.w * rinv * g.w;

    float4 r;
    r.x = e0 * c0 - o0 * s0;
    r.y = o0 * c0 + e0 * s0;
    r.z = e1 * c1 - o1 * s1;
    r.w = o1 * c1 + e1 * s1;
    ((float4*)row)[t] = r;
}

// ---------------------------------------------------------------------------
// Causal flash attention. Block = 64 queries of one (b,h). 256 threads.
// Score mapping: (qg = tid/16, kg = tid%16), 4q x 4k micro-tile, keys strided
// (kg + 16j) for conflict-light smem reads. Output mapping: q = tid/4,
// d-chunk = (tid%4)*16.
// ---------------------------------------------------------------------------
#define FPAD 68
#define FLASH_SMEM ((4*64*FPAD + 3*64) * (int)sizeof(float))

__global__ void __launch_bounds__(256) flash_kernel(const float* __restrict__ Qg,
                                                    const float* __restrict__ Kg,
                                                    const float* __restrict__ Vg,
                                                    float* __restrict__ Og)
{
    extern __shared__ float sm[];
    float* Qs    = sm;
    float* Ks    = Qs + 64 * FPAD;
    float* Vs    = Ks + 64 * FPAD;
    float* Ps    = Vs + 64 * FPAD;
    float* row_m = Ps + 64 * FPAD;
    float* row_a = row_m + 64;
    float* row_s = row_a + 64;

    const int tid = threadIdx.x;
    const int b = blockIdx.z, h = blockIdx.y;
    const int q0 = blockIdx.x * 64;

    const size_t base = ((size_t)b * Sq) * Dq + (size_t)h * DKq;

    const int lchunk = tid & 15;     // float4 within a 64-float row
    const int lrow   = tid >> 4;

    // load Q tile
    {
        const float* Qrow = Qg + base + (size_t)q0 * Dq;
#pragma unroll
        for (int rr = 0; rr < 64; rr += 16) {
            int r = lrow + rr;
            *(float4*)(Qs + r * FPAD + lchunk * 4) =
                *(const float4*)(Qrow + (size_t)r * Dq + lchunk * 4);
        }
    }
    if (tid < 64) row_m[tid] = -1e30f;

    const int qg = tid >> 4, kg = tid & 15;
    const int qb = tid >> 2, cb = tid & 3;

    float acc[16];
#pragma unroll
    for (int i = 0; i < 16; i++) acc[i] = 0.f;
    float l_reg = 0.f;

    const int ntiles = blockIdx.x + 1;     // causal: keys <= q0+63
    for (int t = 0; t < ntiles; t++) {
        const int k0 = t * 64;
        __syncthreads();    // previous tile's consumers done before overwrite
        {
            const float* Krow = Kg + base + (size_t)k0 * Dq;
            const float* Vrow = Vg + base + (size_t)k0 * Dq;
#pragma unroll
            for (int rr = 0; rr < 64; rr += 16) {
                int r = lrow + rr;
                *(float4*)(Ks + r * FPAD + lchunk * 4) =
                    *(const float4*)(Krow + (size_t)r * Dq + lchunk * 4);
                *(float4*)(Vs + r * FPAD + lchunk * 4) =
                    *(const float4*)(Vrow + (size_t)r * Dq + lchunk * 4);
            }
        }
        __syncthreads();

        // S = Q K^T tile (4x4 per thread)
        float sc[4][4];
#pragma unroll
        for (int i = 0; i < 4; i++)
#pragma unroll
            for (int j = 0; j < 4; j++) sc[i][j] = 0.f;

#pragma unroll
        for (int d = 0; d < 64; d += 4) {
            float4 qv[4], kv[4];
#pragma unroll
            for (int i = 0; i < 4; i++)
                qv[i] = *(const float4*)(Qs + (qg * 4 + i) * FPAD + d);
#pragma unroll
            for (int j = 0; j < 4; j++)
                kv[j] = *(const float4*)(Ks + (kg + 16 * j) * FPAD + d);
#pragma unroll
            for (int i = 0; i < 4; i++)
#pragma unroll
                for (int j = 0; j < 4; j++)
                    sc[i][j] += qv[i].x * kv[j].x + qv[i].y * kv[j].y
                              + qv[i].z * kv[j].z + qv[i].w * kv[j].w;
        }

        const bool diag = (t == blockIdx.x);
#pragma unroll
        for (int i = 0; i < 4; i++) {
            const int q = qg * 4 + i;
#pragma unroll
            for (int j = 0; j < 4; j++) {
                float v = sc[i][j] * 0.125f;                 // 1/sqrt(64)
                if (diag && (k0 + kg + 16 * j) > (q0 + q)) v = -1e30f;
                sc[i][j] = v;
            }
        }

        // online softmax per query row (16-lane groups within a warp)
#pragma unroll
        for (int i = 0; i < 4; i++) {
            const int q = qg * 4 + i;
            float mx = fmaxf(fmaxf(sc[i][0], sc[i][1]), fmaxf(sc[i][2], sc[i][3]));
#pragma unroll
            for (int o = 8; o > 0; o >>= 1)
                mx = fmaxf(mx, __shfl_xor_sync(0xffffffffu, mx, o));
            const float m_old = row_m[q];
            const float m_new = fmaxf(m_old, mx);
            float ssum = 0.f;
#pragma unroll
            for (int j = 0; j < 4; j++) {
                float p = expf(sc[i][j] - m_new);
                sc[i][j] = p;
                ssum += p;
            }
#pragma unroll
            for (int o = 8; o > 0; o >>= 1)
                ssum += __shfl_xor_sync(0xffffffffu, ssum, o);
#pragma unroll
            for (int j = 0; j < 4; j++)
                Ps[q * FPAD + kg + 16 * j] = sc[i][j];
            if (kg == 0) {
                row_a[q] = expf(m_old - m_new);
                row_s[q] = ssum;
                row_m[q] = m_new;
            }
        }
        __syncthreads();

        // O += P V  (remapped: one q row, 16 contiguous dims per thread)
        const float alpha = row_a[qb];
        l_reg = l_reg * alpha + row_s[qb];
#pragma unroll
        for (int i = 0; i < 16; i++) acc[i] *= alpha;

#pragma unroll 8
        for (int kk = 0; kk < 64; kk++) {
            const float p = Ps[qb * FPAD + kk];
            const float* vr = Vs + kk * FPAD + cb * 16;
            float4 v0 = *(const float4*)(vr);
            float4 v1 = *(const float4*)(vr + 4);
            float4 v2 = *(const float4*)(vr + 8);
            float4 v3 = *(const float4*)(vr + 12);
            acc[ 0] += p * v0.x; acc[ 1] += p * v0.y; acc[ 2] += p * v0.z; acc[ 3] += p * v0.w;
            acc[ 4] += p * v1.x; acc[ 5] += p * v1.y; acc[ 6] += p * v1.z; acc[ 7] += p * v1.w;
            acc[ 8] += p * v2.x; acc[ 9] += p * v2.y; acc[10] += p * v2.z; acc[11] += p * v2.w;
            acc[12] += p * v3.x; acc[13] += p * v3.y; acc[14] += p * v3.z; acc[15] += p * v3.w;
        }
    }

    const float inv_l = 1.0f / l_reg;
    float* Orow = Og + base + (size_t)(q0 + qb) * Dq + cb * 16;
#pragma unroll
    for (int ii = 0; ii < 4; ii++) {
        float4 o4 = make_float4(acc[ii * 4 + 0] * inv_l, acc[ii * 4 + 1] * inv_l,
                                acc[ii * 4 + 2] * inv_l, acc[ii * 4 + 3] * inv_l);
        *(float4*)(Orow + ii * 4) = o4;
    }
}

// ---------------------------------------------------------------------------
extern "C" void kernel_launch(void* const* d_in, const int* in_sizes, int n_in,
                              void* d_out, int out_size)
{
    const float* x    = (const float*)d_in[0];
    const float* W_Q  = (const float*)d_in[1];
    const float* W_K  = (const float*)d_in[2];
    const float* W_V  = (const float*)d_in[3];
    const float* W_O  = (const float*)d_in[4];
    const float* gain = (const float*)d_in[5];
    float* out = (float*)d_out;

    float *Qp, *Kp, *Vp, *AOp;
    cudaGetSymbolAddress((void**)&Qp,  g_Q);
    cudaGetSymbolAddress((void**)&Kp,  g_K);
    cudaGetSymbolAddress((void**)&Vp,  g_V);
    cudaGetSymbolAddress((void**)&AOp, g_AO);

    dim3 gg(Dq / 128, NR / 128);   // (8, 32)

    gemm_nt<<<gg, 256>>>(x, W_Q, Qp, NR, Dq, Dq);
    gemm_nt<<<gg, 256>>>(x, W_K, Kp, NR, Dq, Dq);
    gemm_nt<<<gg, 256>>>(x, W_V, Vp, NR, Dq, Dq);

    norm_rope_kernel<<<NR, 256>>>(Qp, gain);
    norm_rope_kernel<<<NR, 256>>>(Kp, gain);

    cudaFuncSetAttribute(flash_kernel,
                         cudaFuncAttributeMaxDynamicSharedMemorySize, FLASH_SMEM);
    flash_kernel<<<dim3(Sq / 64, Hq, Bq), 256, FLASH_SMEM>>>(Qp, Kp, Vp, AOp);

    gemm_nt<<<gg, 256>>>(AOp, W_O, out, NR, Dq, Dq);
}

// round 3
// speedup vs baseline: 1.3659x; 1.3659x over previous
#include <cuda_runtime.h>
#include <cuda_bf16.h>
#include <math.h>
#include <stdint.h>

// Problem constants (fixed by dataset)
#define Bq   2
#define Sq   2048
#define Dq   1024
#define Hq   16
#define DKq  64
#define NR   (Bq*Sq)          // 4096 token rows

// ---------------------------------------------------------------------------
// Scratch (allocation-free rule: __device__ globals)
// ---------------------------------------------------------------------------
__device__ float g_Q [NR*Dq];
__device__ float g_K [NR*Dq];
__device__ float g_V [NR*Dq];
__device__ float g_AO[NR*Dq];
__device__ __nv_bfloat16 g_xh [NR*Dq];
__device__ __nv_bfloat16 g_xl [NR*Dq];
__device__ __nv_bfloat16 g_aoh[NR*Dq];
__device__ __nv_bfloat16 g_aol[NR*Dq];
__device__ __nv_bfloat16 g_Wh [4*Dq*Dq];   // WQ,WK,WV,WO hi
__device__ __nv_bfloat16 g_Wl [4*Dq*Dq];   // lo
__device__ float g_sin[Sq*32];
__device__ float g_cos[Sq*32];

// ---------------------------------------------------------------------------
// mma.sync helpers (target-independent PTX -> HMMA on sm_103)
// ---------------------------------------------------------------------------
__device__ __forceinline__ void mma_bf16(float* d, const uint32_t* a, const uint32_t* b) {
    asm volatile(
        "mma.sync.aligned.m16n8k16.row.col.f32.bf16.bf16.f32 "
        "{%0,%1,%2,%3}, {%4,%5,%6,%7}, {%8,%9}, {%0,%1,%2,%3};\n"
        : "+f"(d[0]), "+f"(d[1]), "+f"(d[2]), "+f"(d[3])
        : "r"(a[0]), "r"(a[1]), "r"(a[2]), "r"(a[3]), "r"(b[0]), "r"(b[1]));
}

__device__ __forceinline__ void ldsm_x4(uint32_t* r, uint32_t addr) {
    asm volatile("ldmatrix.sync.aligned.m8n8.x4.shared.b16 {%0,%1,%2,%3}, [%4];"
        : "=r"(r[0]), "=r"(r[1]), "=r"(r[2]), "=r"(r[3]) : "r"(addr));
}
__device__ __forceinline__ void ldsm_x2(uint32_t* r, uint32_t addr) {
    asm volatile("ldmatrix.sync.aligned.m8n8.x2.shared.b16 {%0,%1}, [%2];"
        : "=r"(r[0]), "=r"(r[1]) : "r"(addr));
}

__device__ __forceinline__ uint32_t smem_u32(const void* p) {
    uint32_t a;
    asm("{ .reg .u64 t; cvta.to.shared.u64 t, %1; cvt.u32.u64 %0, t; }"
        : "=r"(a) : "l"(p));
    return a;
}

// ---------------------------------------------------------------------------
// fp32 -> (bf16 hi, bf16 lo) split. One float4 per thread.
// ---------------------------------------------------------------------------
__global__ void __launch_bounds__(256) split_kernel(const float* __restrict__ X,
                                                    __nv_bfloat16* __restrict__ H,
                                                    __nv_bfloat16* __restrict__ L,
                                                    int n4)
{
    int i = blockIdx.x * 256 + threadIdx.x;
    if (i >= n4) return;
    float4 v = ((const float4*)X)[i];
    float f[4] = {v.x, v.y, v.z, v.w};
    __nv_bfloat16 h[4], l[4];
#pragma unroll
    for (int j = 0; j < 4; j++) {
        h[j] = __float2bfloat16(f[j]);
        l[j] = __float2bfloat16(f[j] - __bfloat162float(h[j]));
    }
    __nv_bfloat162* H2 = (__nv_bfloat162*)H;
    __nv_bfloat162* L2 = (__nv_bfloat162*)L;
    H2[2*i]   = __nv_bfloat162(h[0], h[1]);
    H2[2*i+1] = __nv_bfloat162(h[2], h[3]);
    L2[2*i]   = __nv_bfloat162(l[0], l[1]);
    L2[2*i+1] = __nv_bfloat162(l[2], l[3]);
}

// ---------------------------------------------------------------------------
// Split-bf16 tensor-core GEMM via mma.sync: C[m,n] = sum_k A[m,k]*W[n,k].
// CTA 128x128, 8 warps (2x4) of 64x32, K-chunk 64, 3 passes (AhBh+AlBh+AhBl).
// Smem tiles: 128 rows x 64 bf16, padded row stride 72 halfwords (144 B).
// ---------------------------------------------------------------------------
#define GSTRIDE 72                       // halfwords per smem row
#define GTILE   (128 * GSTRIDE)          // halfwords per tile
#define GEMM_SMEM (4 * GTILE * 2)        // bytes: Ah, Al, Bh, Bl

__global__ void __launch_bounds__(256) gemm_tc(const __nv_bfloat16* __restrict__ Ah,
                                               const __nv_bfloat16* __restrict__ Al,
                                               const __nv_bfloat16* __restrict__ Bh,
                                               const __nv_bfloat16* __restrict__ Bl,
                                               float* __restrict__ C,
                                               int M, int N, int K)
{
    extern __shared__ __nv_bfloat16 smg[];
    __nv_bfloat16* sAh = smg;
    __nv_bfloat16* sAl = smg + GTILE;
    __nv_bfloat16* sBh = smg + 2 * GTILE;
    __nv_bfloat16* sBl = smg + 3 * GTILE;

    const int tid  = threadIdx.x;
    const int lane = tid & 31;
    const int wid  = tid >> 5;
    const int bm   = blockIdx.y * 128;
    const int bn   = blockIdx.x * 128;
    const int wm   = (wid >> 2) * 64;     // 0 / 64
    const int wn   = (wid & 3) * 32;      // 0..96

    const uint32_t sb = smem_u32(smg);
    const uint32_t aAh = sb;
    const uint32_t aAl = sb + GTILE * 2;
    const uint32_t aBh = sb + 2 * GTILE * 2;
    const uint32_t aBl = sb + 3 * GTILE * 2;

    float acc[4][4][4];
#pragma unroll
    for (int mt = 0; mt < 4; mt++)
#pragma unroll
        for (int nt = 0; nt < 4; nt++)
#pragma unroll
            for (int r = 0; r < 4; r++) acc[mt][nt][r] = 0.f;

    // ldmatrix per-lane byte offsets (within a tile)
    const uint32_t offA = ((lane & 15) * GSTRIDE + (lane >> 4) * 8) * 2;
    const uint32_t offB = ((lane & 7) * GSTRIDE + ((lane >> 3) & 1) * 8) * 2;

    const int KT = K / 64;
    for (int kt = 0; kt < KT; kt++) {
        const int k0 = kt * 64;
        __syncthreads();
        // load 4 tiles of 128x64 bf16 (8 uint4 per row)
#pragma unroll
        for (int j = 0; j < 4; j++) {
            int idx = tid + j * 256;          // 0..1023
            int row = idx >> 3;
            int cq  = idx & 7;
            uint32_t so = (uint32_t)(row * GSTRIDE + cq * 8);
            size_t ga = (size_t)(bm + row) * K + k0 + cq * 8;
            size_t gb = (size_t)(bn + row) * K + k0 + cq * 8;
            *(uint4*)(sAh + so) = *(const uint4*)(Ah + ga);
            *(uint4*)(sAl + so) = *(const uint4*)(Al + ga);
            *(uint4*)(sBh + so) = *(const uint4*)(Bh + gb);
            *(uint4*)(sBl + so) = *(const uint4*)(Bl + gb);
        }
        __syncthreads();

#pragma unroll
        for (int ks = 0; ks < 4; ks++) {
            const uint32_t kof = (uint32_t)(ks * 16 * 2);
            uint32_t bh[4][2], bl[4][2], af[4][4];
#pragma unroll
            for (int nt = 0; nt < 4; nt++) {
                uint32_t ro = (uint32_t)((wn + nt * 8) * GSTRIDE * 2) + kof;
                ldsm_x2(bh[nt], aBh + ro + offB);
                ldsm_x2(bl[nt], aBl + ro + offB);
            }
#pragma unroll
            for (int mt = 0; mt < 4; mt++) {
                uint32_t ro = (uint32_t)((wm + mt * 16) * GSTRIDE * 2) + kof;
                ldsm_x4(af[mt], aAh + ro + offA);
            }
#pragma unroll
            for (int mt = 0; mt < 4; mt++)
#pragma unroll
                for (int nt = 0; nt < 4; nt++) {
                    mma_bf16(acc[mt][nt], af[mt], bh[nt]);
                    mma_bf16(acc[mt][nt], af[mt], bl[nt]);
                }
#pragma unroll
            for (int mt = 0; mt < 4; mt++) {
                uint32_t ro = (uint32_t)((wm + mt * 16) * GSTRIDE * 2) + kof;
                ldsm_x4(af[mt], aAl + ro + offA);
            }
#pragma unroll
            for (int mt = 0; mt < 4; mt++)
#pragma unroll
                for (int nt = 0; nt < 4; nt++)
                    mma_bf16(acc[mt][nt], af[mt], bh[nt]);
        }
    }

    // epilogue: d0,d1 -> (row, col..col+1); d2,d3 -> (row+8, ...)
    const int er = lane >> 2;
    const int ec = (lane & 3) * 2;
#pragma unroll
    for (int mt = 0; mt < 4; mt++) {
        const int row = bm + wm + mt * 16 + er;
#pragma unroll
        for (int nt = 0; nt < 4; nt++) {
            const int col = bn + wn + nt * 8 + ec;
            *(float2*)(C + (size_t)row * N + col) =
                make_float2(acc[mt][nt][0], acc[mt][nt][1]);
            *(float2*)(C + (size_t)(row + 8) * N + col) =
                make_float2(acc[mt][nt][2], acc[mt][nt][3]);
        }
    }
}

// ---------------------------------------------------------------------------
// RoPE table: sin/cos[s][p] for s<2048, p<32. Exact (double) inv_freq.
// ---------------------------------------------------------------------------
__global__ void __launch_bounds__(256) rope_table_kernel(float* __restrict__ st,
                                                         float* __restrict__ ct)
{
    int i = blockIdx.x * 256 + threadIdx.x;   // 65536
    int s = i >> 5, p = i & 31;
    double f = exp(-(double)p * (9.210340371976184 / 32.0));
    float a = (float)((double)s * f);
    float sv, cv;
    sincosf(a, &sv, &cv);
    st[i] = sv;
    ct[i] = cv;
}

// ---------------------------------------------------------------------------
// Fused RMSNorm (full D=1024) + RoPE (table lookup), in place.
// ---------------------------------------------------------------------------
__global__ void __launch_bounds__(256) norm_rope_kernel(float* __restrict__ T,
                                                        const float* __restrict__ gain,
                                                        const float* __restrict__ st,
                                                        const float* __restrict__ ct)
{
    const int n = blockIdx.x;
    const int s = n % Sq;
    float* row = T + (size_t)n * Dq;
    const int t = threadIdx.x;

    float4 x = ((float4*)row)[t];
    float ss = x.x * x.x + x.y * x.y + x.z * x.z + x.w * x.w;
#pragma unroll
    for (int o = 16; o > 0; o >>= 1) ss += __shfl_xor_sync(0xffffffffu, ss, o);

    __shared__ float wsum[8];
    if ((t & 31) == 0) wsum[t >> 5] = ss;
    __syncthreads();
    float tot = 0.f;
#pragma unroll
    for (int i = 0; i < 8; i++) tot += wsum[i];

    const float rinv = rsqrtf(tot * (1.0f / 1024.0f) + 1e-5f);
    const float4 g = ((const float4*)gain)[t];

    const int p0 = ((t * 4) & 63) >> 1;
    const float s0 = st[s * 32 + p0],     c0 = ct[s * 32 + p0];
    const float s1 = st[s * 32 + p0 + 1], c1 = ct[s * 32 + p0 + 1];

    const float e0 = x.x * rinv * g.x, o0 = x.y * rinv * g.y;
    const float e1 = x.z * rinv * g.z, o1 = x.w * rinv * g.w;

    float4 r;
    r.x = e0 * c0 - o0 * s0;
    r.y = o0 * c0 + e0 * s0;
    r.z = e1 * c1 - o1 * s1;
    r.w = o1 * c1 + e1 * s1;
    ((float4*)row)[t] = r;
}

// ---------------------------------------------------------------------------
// Causal flash attention (SIMT). Block = 64 queries of one (b,h).
// ---------------------------------------------------------------------------
#define FPAD 68
#define FLASH_SMEM ((4*64*FPAD + 3*64) * (int)sizeof(float))

__global__ void __launch_bounds__(256) flash_kernel(const float* __restrict__ Qg,
                                                    const float* __restrict__ Kg,
                                                    const float* __restrict__ Vg,
                                                    float* __restrict__ Og)
{
    extern __shared__ float sm[];
    float* Qs    = sm;
    float* Ks    = Qs + 64 * FPAD;
    float* Vs    = Ks + 64 * FPAD;
    float* Ps    = Vs + 64 * FPAD;
    float* row_m = Ps + 64 * FPAD;
    float* row_a = row_m + 64;
    float* row_s = row_a + 64;

    const int tid = threadIdx.x;
    const int b = blockIdx.z, h = blockIdx.y;
    const int q0 = blockIdx.x * 64;

    const size_t base = ((size_t)b * Sq) * Dq + (size_t)h * DKq;

    const int lchunk = tid & 15;
    const int lrow   = tid >> 4;

    {
        const float* Qrow = Qg + base + (size_t)q0 * Dq;
#pragma unroll
        for (int rr = 0; rr < 64; rr += 16) {
            int r = lrow + rr;
            *(float4*)(Qs + r * FPAD + lchunk * 4) =
                *(const float4*)(Qrow + (size_t)r * Dq + lchunk * 4);
        }
    }
    if (tid < 64) row_m[tid] = -1e30f;

    const int qg = tid >> 4, kg = tid & 15;
    const int qb = tid >> 2, cb = tid & 3;

    float acc[16];
#pragma unroll
    for (int i = 0; i < 16; i++) acc[i] = 0.f;
    float l_reg = 0.f;

    const int ntiles = blockIdx.x + 1;
    for (int t = 0; t < ntiles; t++) {
        const int k0 = t * 64;
        __syncthreads();
        {
            const float* Krow = Kg + base + (size_t)k0 * Dq;
            const float* Vrow = Vg + base + (size_t)k0 * Dq;
#pragma unroll
            for (int rr = 0; rr < 64; rr += 16) {
                int r = lrow + rr;
                *(float4*)(Ks + r * FPAD + lchunk * 4) =
                    *(const float4*)(Krow + (size_t)r * Dq + lchunk * 4);
                *(float4*)(Vs + r * FPAD + lchunk * 4) =
                    *(const float4*)(Vrow + (size_t)r * Dq + lchunk * 4);
            }
        }
        __syncthreads();

        float sc[4][4];
#pragma unroll
        for (int i = 0; i < 4; i++)
#pragma unroll
            for (int j = 0; j < 4; j++) sc[i][j] = 0.f;

#pragma unroll
        for (int d = 0; d < 64; d += 4) {
            float4 qv[4], kv[4];
#pragma unroll
            for (int i = 0; i < 4; i++)
                qv[i] = *(const float4*)(Qs + (qg * 4 + i) * FPAD + d);
#pragma unroll
            for (int j = 0; j < 4; j++)
                kv[j] = *(const float4*)(Ks + (kg + 16 * j) * FPAD + d);
#pragma unroll
            for (int i = 0; i < 4; i++)
#pragma unroll
                for (int j = 0; j < 4; j++)
                    sc[i][j] += qv[i].x * kv[j].x + qv[i].y * kv[j].y
                              + qv[i].z * kv[j].z + qv[i].w * kv[j].w;
        }

        const bool diag = (t == blockIdx.x);
#pragma unroll
        for (int i = 0; i < 4; i++) {
            const int q = qg * 4 + i;
#pragma unroll
            for (int j = 0; j < 4; j++) {
                float v = sc[i][j] * 0.125f;
                if (diag && (k0 + kg + 16 * j) > (q0 + q)) v = -1e30f;
                sc[i][j] = v;
            }
        }

#pragma unroll
        for (int i = 0; i < 4; i++) {
            const int q = qg * 4 + i;
            float mx = fmaxf(fmaxf(sc[i][0], sc[i][1]), fmaxf(sc[i][2], sc[i][3]));
#pragma unroll
            for (int o = 8; o > 0; o >>= 1)
                mx = fmaxf(mx, __shfl_xor_sync(0xffffffffu, mx, o));
            const float m_old = row_m[q];
            const float m_new = fmaxf(m_old, mx);
            float ssum = 0.f;
#pragma unroll
            for (int j = 0; j < 4; j++) {
                float p = expf(sc[i][j] - m_new);
                sc[i][j] = p;
                ssum += p;
            }
#pragma unroll
            for (int o = 8; o > 0; o >>= 1)
                ssum += __shfl_xor_sync(0xffffffffu, ssum, o);
#pragma unroll
            for (int j = 0; j < 4; j++)
                Ps[q * FPAD + kg + 16 * j] = sc[i][j];
            if (kg == 0) {
                row_a[q] = expf(m_old - m_new);
                row_s[q] = ssum;
                row_m[q] = m_new;
            }
        }
        __syncthreads();

        const float alpha = row_a[qb];
        l_reg = l_reg * alpha + row_s[qb];
#pragma unroll
        for (int i = 0; i < 16; i++) acc[i] *= alpha;

#pragma unroll 8
        for (int kk = 0; kk < 64; kk++) {
            const float p = Ps[qb * FPAD + kk];
            const float* vr = Vs + kk * FPAD + cb * 16;
            float4 v0 = *(const float4*)(vr);
            float4 v1 = *(const float4*)(vr + 4);
            float4 v2 = *(const float4*)(vr + 8);
            float4 v3 = *(const float4*)(vr + 12);
            acc[ 0] += p * v0.x; acc[ 1] += p * v0.y; acc[ 2] += p * v0.z; acc[ 3] += p * v0.w;
            acc[ 4] += p * v1.x; acc[ 5] += p * v1.y; acc[ 6] += p * v1.z; acc[ 7] += p * v1.w;
            acc[ 8] += p * v2.x; acc[ 9] += p * v2.y; acc[10] += p * v2.z; acc[11] += p * v2.w;
            acc[12] += p * v3.x; acc[13] += p * v3.y; acc[14] += p * v3.z; acc[15] += p * v3.w;
        }
    }

    const float inv_l = 1.0f / l_reg;
    float* Orow = Og + base + (size_t)(q0 + qb) * Dq + cb * 16;
#pragma unroll
    for (int ii = 0; ii < 4; ii++) {
        float4 o4 = make_float4(acc[ii * 4 + 0] * inv_l, acc[ii * 4 + 1] * inv_l,
                                acc[ii * 4 + 2] * inv_l, acc[ii * 4 + 3] * inv_l);
        *(float4*)(Orow + ii * 4) = o4;
    }
}

// ---------------------------------------------------------------------------
extern "C" void kernel_launch(void* const* d_in, const int* in_sizes, int n_in,
                              void* d_out, int out_size)
{
    const float* x    = (const float*)d_in[0];
    const float* W_Q  = (const float*)d_in[1];
    const float* W_K  = (const float*)d_in[2];
    const float* W_V  = (const float*)d_in[3];
    const float* W_O  = (const float*)d_in[4];
    const float* gain = (const float*)d_in[5];
    float* out = (float*)d_out;

    float *Qp, *Kp, *Vp, *AOp, *sinp, *cosp;
    __nv_bfloat16 *xh, *xl, *aoh, *aol, *Wh, *Wl;
    cudaGetSymbolAddress((void**)&Qp,   g_Q);
    cudaGetSymbolAddress((void**)&Kp,   g_K);
    cudaGetSymbolAddress((void**)&Vp,   g_V);
    cudaGetSymbolAddress((void**)&AOp,  g_AO);
    cudaGetSymbolAddress((void**)&sinp, g_sin);
    cudaGetSymbolAddress((void**)&cosp, g_cos);
    cudaGetSymbolAddress((void**)&xh,   g_xh);
    cudaGetSymbolAddress((void**)&xl,   g_xl);
    cudaGetSymbolAddress((void**)&aoh,  g_aoh);
    cudaGetSymbolAddress((void**)&aol,  g_aol);
    cudaGetSymbolAddress((void**)&Wh,   g_Wh);
    cudaGetSymbolAddress((void**)&Wl,   g_Wl);

    cudaFuncSetAttribute(gemm_tc,
                         cudaFuncAttributeMaxDynamicSharedMemorySize, GEMM_SMEM);
    cudaFuncSetAttribute(flash_kernel,
                         cudaFuncAttributeMaxDynamicSharedMemorySize, FLASH_SMEM);

    const int nx4 = NR * Dq / 4;       // 1M float4
    const int nw4 = Dq * Dq / 4;       // 256K float4
    const size_t WSZ = (size_t)Dq * Dq;

    // splits + table
    split_kernel<<<nx4 / 256, 256>>>(x, xh, xl, nx4);
    split_kernel<<<nw4 / 256, 256>>>(W_Q, Wh + 0*WSZ, Wl + 0*WSZ, nw4);
    split_kernel<<<nw4 / 256, 256>>>(W_K, Wh + 1*WSZ, Wl + 1*WSZ, nw4);
    split_kernel<<<nw4 / 256, 256>>>(W_V, Wh + 2*WSZ, Wl + 2*WSZ, nw4);
    split_kernel<<<nw4 / 256, 256>>>(W_O, Wh + 3*WSZ, Wl + 3*WSZ, nw4);
    rope_table_kernel<<<Sq * 32 / 256, 256>>>(sinp, cosp);

    // projections on tensor cores (mma.sync path)
    dim3 gg(Dq / 128, NR / 128);       // (8, 32)
    gemm_tc<<<gg, 256, GEMM_SMEM>>>(xh, xl, Wh + 0*WSZ, Wl + 0*WSZ, Qp, NR, Dq, Dq);
    gemm_tc<<<gg, 256, GEMM_SMEM>>>(xh, xl, Wh + 1*WSZ, Wl + 1*WSZ, Kp, NR, Dq, Dq);
    gemm_tc<<<gg, 256, GEMM_SMEM>>>(xh, xl, Wh + 2*WSZ, Wl + 2*WSZ, Vp, NR, Dq, Dq);

    norm_rope_kernel<<<NR, 256>>>(Qp, gain, sinp, cosp);
    norm_rope_kernel<<<NR, 256>>>(Kp, gain, sinp, cosp);

    flash_kernel<<<dim3(Sq / 64, Hq, Bq), 256, FLASH_SMEM>>>(Qp, Kp, Vp, AOp);

    split_kernel<<<nx4 / 256, 256>>>(AOp, aoh, aol, nx4);
    gemm_tc<<<gg, 256, GEMM_SMEM>>>(aoh, aol, Wh + 3*WSZ, Wl + 3*WSZ, out, NR, Dq, Dq);
}

// round 4
// speedup vs baseline: 4.1118x; 3.0103x over previous
#include <cuda_runtime.h>
#include <cuda_bf16.h>
#include <math.h>
#include <stdint.h>

// Problem constants (fixed by dataset)
#define Bq   2
#define Sq   2048
#define Dq   1024
#define Hq   16
#define DKq  64
#define NR   (Bq*Sq)          // 4096 token rows

// ---------------------------------------------------------------------------
// Scratch (allocation-free rule: __device__ globals)
// ---------------------------------------------------------------------------
__device__ float g_Q [NR*Dq];
__device__ float g_K [NR*Dq];
__device__ float g_V [NR*Dq];
__device__ __nv_bfloat16 g_xh [NR*Dq];
__device__ __nv_bfloat16 g_xl [NR*Dq];
__device__ __nv_bfloat16 g_aoh[NR*Dq];
__device__ __nv_bfloat16 g_aol[NR*Dq];
__device__ __nv_bfloat16 g_Qh [NR*Dq];
__device__ __nv_bfloat16 g_Ql [NR*Dq];
__device__ __nv_bfloat16 g_Kh [NR*Dq];
__device__ __nv_bfloat16 g_Kl [NR*Dq];
__device__ __nv_bfloat16 g_Vh [NR*Dq];
__device__ __nv_bfloat16 g_Vl [NR*Dq];
__device__ __nv_bfloat16 g_Wh [4*Dq*Dq];   // WQ,WK,WV,WO hi
__device__ __nv_bfloat16 g_Wl [4*Dq*Dq];   // lo
__device__ float g_sin[Sq*32];
__device__ float g_cos[Sq*32];

// ---------------------------------------------------------------------------
// mma.sync helpers (target-independent PTX -> HMMA on sm_103)
// ---------------------------------------------------------------------------
__device__ __forceinline__ void mma_bf16(float* d, const uint32_t* a, const uint32_t* b) {
    asm volatile(
        "mma.sync.aligned.m16n8k16.row.col.f32.bf16.bf16.f32 "
        "{%0,%1,%2,%3}, {%4,%5,%6,%7}, {%8,%9}, {%0,%1,%2,%3};\n"
        : "+f"(d[0]), "+f"(d[1]), "+f"(d[2]), "+f"(d[3])
        : "r"(a[0]), "r"(a[1]), "r"(a[2]), "r"(a[3]), "r"(b[0]), "r"(b[1]));
}

__device__ __forceinline__ void ldsm_x4(uint32_t* r, uint32_t addr) {
    asm volatile("ldmatrix.sync.aligned.m8n8.x4.shared.b16 {%0,%1,%2,%3}, [%4];"
        : "=r"(r[0]), "=r"(r[1]), "=r"(r[2]), "=r"(r[3]) : "r"(addr));
}
__device__ __forceinline__ void ldsm_x4_t(uint32_t* r, uint32_t addr) {
    asm volatile("ldmatrix.sync.aligned.m8n8.x4.trans.shared.b16 {%0,%1,%2,%3}, [%4];"
        : "=r"(r[0]), "=r"(r[1]), "=r"(r[2]), "=r"(r[3]) : "r"(addr));
}
__device__ __forceinline__ void ldsm_x2(uint32_t* r, uint32_t addr) {
    asm volatile("ldmatrix.sync.aligned.m8n8.x2.shared.b16 {%0,%1}, [%2];"
        : "=r"(r[0]), "=r"(r[1]) : "r"(addr));
}

__device__ __forceinline__ uint32_t smem_u32(const void* p) {
    uint32_t a;
    asm("{ .reg .u64 t; cvta.to.shared.u64 t, %1; cvt.u32.u64 %0, t; }"
        : "=r"(a) : "l"(p));
    return a;
}

__device__ __forceinline__ uint32_t pack_bf16(float a, float b) {
    __nv_bfloat162 t = __floats2bfloat162_rn(a, b);
    return *reinterpret_cast<uint32_t*>(&t);
}

// ---------------------------------------------------------------------------
// fp32 -> (bf16 hi, bf16 lo) split with optional scale. One float4 per thread.
// ---------------------------------------------------------------------------
__global__ void __launch_bounds__(256) split_kernel(const float* __restrict__ X,
                                                    __nv_bfloat16* __restrict__ H,
                                                    __nv_bfloat16* __restrict__ L,
                                                    int n4, float scale)
{
    int i = blockIdx.x * 256 + threadIdx.x;
    if (i >= n4) return;
    float4 v = ((const float4*)X)[i];
    float f[4] = {v.x * scale, v.y * scale, v.z * scale, v.w * scale};
    __nv_bfloat16 h[4], l[4];
#pragma unroll
    for (int j = 0; j < 4; j++) {
        h[j] = __float2bfloat16(f[j]);
        l[j] = __float2bfloat16(f[j] - __bfloat162float(h[j]));
    }
    __nv_bfloat162* H2 = (__nv_bfloat162*)H;
    __nv_bfloat162* L2 = (__nv_bfloat162*)L;
    H2[2*i]   = __nv_bfloat162(h[0], h[1]);
    H2[2*i+1] = __nv_bfloat162(h[2], h[3]);
    L2[2*i]   = __nv_bfloat162(l[0], l[1]);
    L2[2*i+1] = __nv_bfloat162(l[2], l[3]);
}

// ---------------------------------------------------------------------------
// Split-bf16 tensor-core GEMM via mma.sync: C[m,n] = sum_k A[m,k]*W[n,k].
// CTA 128x128, 8 warps (2x4) of 64x32, K-chunk 64, 3 passes.
// ---------------------------------------------------------------------------
#define GSTRIDE 72                       // halfwords per smem row
#define GTILE   (128 * GSTRIDE)          // halfwords per tile
#define GEMM_SMEM (4 * GTILE * 2)        // bytes: Ah, Al, Bh, Bl

__global__ void __launch_bounds__(256) gemm_tc(const __nv_bfloat16* __restrict__ Ah,
                                               const __nv_bfloat16* __restrict__ Al,
                                               const __nv_bfloat16* __restrict__ Bh,
                                               const __nv_bfloat16* __restrict__ Bl,
                                               float* __restrict__ C,
                                               int M, int N, int K)
{
    extern __shared__ __nv_bfloat16 smg[];
    __nv_bfloat16* sAh = smg;
    __nv_bfloat16* sAl = smg + GTILE;
    __nv_bfloat16* sBh = smg + 2 * GTILE;
    __nv_bfloat16* sBl = smg + 3 * GTILE;

    const int tid  = threadIdx.x;
    const int lane = tid & 31;
    const int wid  = tid >> 5;
    const int bm   = blockIdx.y * 128;
    const int bn   = blockIdx.x * 128;
    const int wm   = (wid >> 2) * 64;
    const int wn   = (wid & 3) * 32;

    const uint32_t sb = smem_u32(smg);
    const uint32_t aAh = sb;
    const uint32_t aAl = sb + GTILE * 2;
    const uint32_t aBh = sb + 2 * GTILE * 2;
    const uint32_t aBl = sb + 3 * GTILE * 2;

    float acc[4][4][4];
#pragma unroll
    for (int mt = 0; mt < 4; mt++)
#pragma unroll
        for (int nt = 0; nt < 4; nt++)
#pragma unroll
            for (int r = 0; r < 4; r++) acc[mt][nt][r] = 0.f;

    const uint32_t offA = ((lane & 15) * GSTRIDE + (lane >> 4) * 8) * 2;
    const uint32_t offB = ((lane & 7) * GSTRIDE + ((lane >> 3) & 1) * 8) * 2;

    const int KT = K / 64;
    for (int kt = 0; kt < KT; kt++) {
        const int k0 = kt * 64;
        __syncthreads();
#pragma unroll
        for (int j = 0; j < 4; j++) {
            int idx = tid + j * 256;
            int row = idx >> 3;
            int cq  = idx & 7;
            uint32_t so = (uint32_t)(row * GSTRIDE + cq * 8);
            size_t ga = (size_t)(bm + row) * K + k0 + cq * 8;
            size_t gb = (size_t)(bn + row) * K + k0 + cq * 8;
            *(uint4*)(sAh + so) = *(const uint4*)(Ah + ga);
            *(uint4*)(sAl + so) = *(const uint4*)(Al + ga);
            *(uint4*)(sBh + so) = *(const uint4*)(Bh + gb);
            *(uint4*)(sBl + so) = *(const uint4*)(Bl + gb);
        }
        __syncthreads();

#pragma unroll
        for (int ks = 0; ks < 4; ks++) {
            const uint32_t kof = (uint32_t)(ks * 16 * 2);
            uint32_t bh[4][2], bl[4][2], af[4][4];
#pragma unroll
            for (int nt = 0; nt < 4; nt++) {
                uint32_t ro = (uint32_t)((wn + nt * 8) * GSTRIDE * 2) + kof;
                ldsm_x2(bh[nt], aBh + ro + offB);
                ldsm_x2(bl[nt], aBl + ro + offB);
            }
#pragma unroll
            for (int mt = 0; mt < 4; mt++) {
                uint32_t ro = (uint32_t)((wm + mt * 16) * GSTRIDE * 2) + kof;
                ldsm_x4(af[mt], aAh + ro + offA);
            }
#pragma unroll
            for (int mt = 0; mt < 4; mt++)
#pragma unroll
                for (int nt = 0; nt < 4; nt++) {
                    mma_bf16(acc[mt][nt], af[mt], bh[nt]);
                    mma_bf16(acc[mt][nt], af[mt], bl[nt]);
                }
#pragma unroll
            for (int mt = 0; mt < 4; mt++) {
                uint32_t ro = (uint32_t)((wm + mt * 16) * GSTRIDE * 2) + kof;
                ldsm_x4(af[mt], aAl + ro + offA);
            }
#pragma unroll
            for (int mt = 0; mt < 4; mt++)
#pragma unroll
                for (int nt = 0; nt < 4; nt++)
                    mma_bf16(acc[mt][nt], af[mt], bh[nt]);
        }
    }

    const int er = lane >> 2;
    const int ec = (lane & 3) * 2;
#pragma unroll
    for (int mt = 0; mt < 4; mt++) {
        const int row = bm + wm + mt * 16 + er;
#pragma unroll
        for (int nt = 0; nt < 4; nt++) {
            const int col = bn + wn + nt * 8 + ec;
            *(float2*)(C + (size_t)row * N + col) =
                make_float2(acc[mt][nt][0], acc[mt][nt][1]);
            *(float2*)(C + (size_t)(row + 8) * N + col) =
                make_float2(acc[mt][nt][2], acc[mt][nt][3]);
        }
    }
}

// ---------------------------------------------------------------------------
// RoPE table: sin/cos[s][p] for s<2048, p<32. Exact (double) inv_freq.
// ---------------------------------------------------------------------------
__global__ void __launch_bounds__(256) rope_table_kernel(float* __restrict__ st,
                                                         float* __restrict__ ct)
{
    int i = blockIdx.x * 256 + threadIdx.x;
    int s = i >> 5, p = i & 31;
    double f = exp(-(double)p * (9.210340371976184 / 32.0));
    float a = (float)((double)s * f);
    float sv, cv;
    sincosf(a, &sv, &cv);
    st[i] = sv;
    ct[i] = cv;
}

// ---------------------------------------------------------------------------
// Fused RMSNorm (full D=1024) + RoPE (table lookup), in place.
// ---------------------------------------------------------------------------
__global__ void __launch_bounds__(256) norm_rope_kernel(float* __restrict__ T,
                                                        const float* __restrict__ gain,
                                                        const float* __restrict__ st,
                                                        const float* __restrict__ ct)
{
    const int n = blockIdx.x;
    const int s = n % Sq;
    float* row = T + (size_t)n * Dq;
    const int t = threadIdx.x;

    float4 x = ((float4*)row)[t];
    float ss = x.x * x.x + x.y * x.y + x.z * x.z + x.w * x.w;
#pragma unroll
    for (int o = 16; o > 0; o >>= 1) ss += __shfl_xor_sync(0xffffffffu, ss, o);

    __shared__ float wsum[8];
    if ((t & 31) == 0) wsum[t >> 5] = ss;
    __syncthreads();
    float tot = 0.f;
#pragma unroll
    for (int i = 0; i < 8; i++) tot += wsum[i];

    const float rinv = rsqrtf(tot * (1.0f / 1024.0f) + 1e-5f);
    const float4 g = ((const float4*)gain)[t];

    const int p0 = ((t * 4) & 63) >> 1;
    const float s0 = st[s * 32 + p0],     c0 = ct[s * 32 + p0];
    const float s1 = st[s * 32 + p0 + 1], c1 = ct[s * 32 + p0 + 1];

    const float e0 = x.x * rinv * g.x, o0 = x.y * rinv * g.y;
    const float e1 = x.z * rinv * g.z, o1 = x.w * rinv * g.w;

    float4 r;
    r.x = e0 * c0 - o0 * s0;
    r.y = o0 * c0 + e0 * s0;
    r.z = e1 * c1 - o1 * s1;
    r.w = o1 * c1 + e1 * s1;
    ((float4*)row)[t] = r;
}

// ---------------------------------------------------------------------------
// Tensor-core causal flash attention.
// Block = 64 queries of one (b,h), 4 warps (16 q-rows each), key tiles of 64.
// 3-pass split-bf16 for QK^T and PV. Softmax state in registers.
// Writes O directly as bf16 hi/lo (feeds final GEMM).
// ---------------------------------------------------------------------------
#define FSTR 72
#define FTILE (64 * FSTR)                 // halfwords per 64x64 tile
#define FLASH_SMEM (6 * FTILE * 2)        // Qh,Ql,Kh,Kl,Vh,Vl

__global__ void __launch_bounds__(128) flash_tc(
    const __nv_bfloat16* __restrict__ Qh, const __nv_bfloat16* __restrict__ Ql,
    const __nv_bfloat16* __restrict__ Kh, const __nv_bfloat16* __restrict__ Kl,
    const __nv_bfloat16* __restrict__ Vh, const __nv_bfloat16* __restrict__ Vl,
    __nv_bfloat16* __restrict__ AOh, __nv_bfloat16* __restrict__ AOl)
{
    extern __shared__ __nv_bfloat16 smf[];
    __nv_bfloat16* sQh = smf;
    __nv_bfloat16* sQl = smf + FTILE;
    __nv_bfloat16* sKh = smf + 2 * FTILE;
    __nv_bfloat16* sKl = smf + 3 * FTILE;
    __nv_bfloat16* sVh = smf + 4 * FTILE;
    __nv_bfloat16* sVl = smf + 5 * FTILE;

    const int tid  = threadIdx.x;
    const int lane = tid & 31;
    const int warp = tid >> 5;
    const int q0 = blockIdx.x * 64;
    const int h  = blockIdx.y;
    const int b  = blockIdx.z;

    const uint32_t sb  = smem_u32(smf);
    const uint32_t aQh = sb;
    const uint32_t aQl = sb +     FTILE * 2;
    const uint32_t aKh = sb + 2 * FTILE * 2;
    const uint32_t aKl = sb + 3 * FTILE * 2;
    const uint32_t aVh = sb + 4 * FTILE * 2;
    const uint32_t aVl = sb + 5 * FTILE * 2;

    // ---- load Q tile (64 rows x 64 dims) ----
    {
        const size_t gbase = ((size_t)b * Sq + q0) * Dq + h * DKq;
#pragma unroll
        for (int j = 0; j < 4; j++) {
            int idx = tid + j * 128;          // 0..511
            int row = idx >> 3;
            int cq  = idx & 7;
            size_t g = gbase + (size_t)row * Dq + cq * 8;
            uint32_t so = (uint32_t)(row * FSTR + cq * 8);
            *(uint4*)(sQh + so) = *(const uint4*)(Qh + g);
            *(uint4*)(sQl + so) = *(const uint4*)(Ql + g);
        }
    }
    __syncthreads();

    // ---- Q A-fragments (4 k-chunks) ----
    uint32_t qa_h[4][4], qa_l[4][4];
    const uint32_t offA = (uint32_t)(((lane & 15) * FSTR + (lane >> 4) * 8) * 2);
    const uint32_t qwb  = (uint32_t)(warp * 16 * FSTR * 2);
#pragma unroll
    for (int kc = 0; kc < 4; kc++) {
        ldsm_x4(qa_h[kc], aQh + qwb + (uint32_t)(kc * 32) + offA);
        ldsm_x4(qa_l[kc], aQl + qwb + (uint32_t)(kc * 32) + offA);
    }

    float m0 = -1e30f, m1 = -1e30f, l0 = 0.f, l1 = 0.f;
    float oacc[8][4];
#pragma unroll
    for (int nt = 0; nt < 8; nt++)
#pragma unroll
        for (int r = 0; r < 4; r++) oacc[nt][r] = 0.f;

    const int r0g = q0 + warp * 16 + (lane >> 2);

    const int ntiles = blockIdx.x + 1;
    for (int t = 0; t < ntiles; t++) {
        const int k0 = t * 64;
        __syncthreads();
        {
            const size_t kb = ((size_t)b * Sq + k0) * Dq + h * DKq;
#pragma unroll
            for (int j = 0; j < 4; j++) {
                int idx = tid + j * 128;
                int row = idx >> 3;
                int cq  = idx & 7;
                size_t g = kb + (size_t)row * Dq + cq * 8;
                uint32_t so = (uint32_t)(row * FSTR + cq * 8);
                *(uint4*)(sKh + so) = *(const uint4*)(Kh + g);
                *(uint4*)(sKl + so) = *(const uint4*)(Kl + g);
                *(uint4*)(sVh + so) = *(const uint4*)(Vh + g);
                *(uint4*)(sVl + so) = *(const uint4*)(Vl + g);
            }
        }
        __syncthreads();

        // ---- S = Q K^T (scale prefolded into Q) ----
        float sacc[8][4];
#pragma unroll
        for (int nt = 0; nt < 8; nt++)
#pragma unroll
            for (int r = 0; r < 4; r++) sacc[nt][r] = 0.f;

#pragma unroll
        for (int nt = 0; nt < 8; nt++) {
            uint32_t kbh[8], kbl[8];
            uint32_t rb = (uint32_t)(((nt * 8 + (lane & 7)) * FSTR + (lane >> 3) * 8) * 2);
            ldsm_x4(kbh,     aKh + rb);
            ldsm_x4(kbh + 4, aKh + rb + 64);
            ldsm_x4(kbl,     aKl + rb);
            ldsm_x4(kbl + 4, aKl + rb + 64);
#pragma unroll
            for (int kc = 0; kc < 4; kc++) {
                mma_bf16(sacc[nt], qa_h[kc], kbh + kc * 2);
                mma_bf16(sacc[nt], qa_l[kc], kbh + kc * 2);
                mma_bf16(sacc[nt], qa_h[kc], kbl + kc * 2);
            }
        }

        // ---- causal mask (diagonal tile only) ----
        if (t == blockIdx.x) {
            const int cb = k0 + 2 * (lane & 3);
#pragma unroll
            for (int nt = 0; nt < 8; nt++) {
                int c = cb + nt * 8;
                if (c     > r0g)     sacc[nt][0] = -1e30f;
                if (c + 1 > r0g)     sacc[nt][1] = -1e30f;
                if (c     > r0g + 8) sacc[nt][2] = -1e30f;
                if (c + 1 > r0g + 8) sacc[nt][3] = -1e30f;
            }
        }

        // ---- online softmax (rows r0g, r0g+8 per thread-quad) ----
        float mx0 = -1e30f, mx1 = -1e30f;
#pragma unroll
        for (int nt = 0; nt < 8; nt++) {
            mx0 = fmaxf(mx0, fmaxf(sacc[nt][0], sacc[nt][1]));
            mx1 = fmaxf(mx1, fmaxf(sacc[nt][2], sacc[nt][3]));
        }
        mx0 = fmaxf(mx0, __shfl_xor_sync(0xffffffffu, mx0, 1));
        mx0 = fmaxf(mx0, __shfl_xor_sync(0xffffffffu, mx0, 2));
        mx1 = fmaxf(mx1, __shfl_xor_sync(0xffffffffu, mx1, 1));
        mx1 = fmaxf(mx1, __shfl_xor_sync(0xffffffffu, mx1, 2));

        const float m0n = fmaxf(m0, mx0);
        const float m1n = fmaxf(m1, mx1);
        const float a0 = __expf(m0 - m0n);
        const float a1 = __expf(m1 - m1n);

        float rs0 = 0.f, rs1 = 0.f;
#pragma unroll
        for (int nt = 0; nt < 8; nt++) {
            float p0 = __expf(sacc[nt][0] - m0n);
            float p1 = __expf(sacc[nt][1] - m0n);
            float p2 = __expf(sacc[nt][2] - m1n);
            float p3 = __expf(sacc[nt][3] - m1n);
            sacc[nt][0] = p0; sacc[nt][1] = p1; sacc[nt][2] = p2; sacc[nt][3] = p3;
            rs0 += p0 + p1;
            rs1 += p2 + p3;
        }
        rs0 += __shfl_xor_sync(0xffffffffu, rs0, 1);
        rs0 += __shfl_xor_sync(0xffffffffu, rs0, 2);
        rs1 += __shfl_xor_sync(0xffffffffu, rs1, 1);
        rs1 += __shfl_xor_sync(0xffffffffu, rs1, 2);

        l0 = l0 * a0 + rs0;
        l1 = l1 * a1 + rs1;
        m0 = m0n;
        m1 = m1n;
#pragma unroll
        for (int nt = 0; nt < 8; nt++) {
            oacc[nt][0] *= a0; oacc[nt][1] *= a0;
            oacc[nt][2] *= a1; oacc[nt][3] *= a1;
        }

        // ---- convert P -> A-fragments (hi/lo) ----
        uint32_t pa_h[4][4], pa_l[4][4];
#pragma unroll
        for (int kc = 0; kc < 4; kc++) {
#pragma unroll
            for (int half = 0; half < 2; half++) {
                const float* v = sacc[2 * kc + half];
                float h00 = __bfloat162float(__float2bfloat16(v[0]));
                float h01 = __bfloat162float(__float2bfloat16(v[1]));
                float h10 = __bfloat162float(__float2bfloat16(v[2]));
                float h11 = __bfloat162float(__float2bfloat16(v[3]));
                pa_h[kc][0 + 2 * half] = pack_bf16(h00, h01);
                pa_h[kc][1 + 2 * half] = pack_bf16(h10, h11);
                pa_l[kc][0 + 2 * half] = pack_bf16(v[0] - h00, v[1] - h01);
                pa_l[kc][1 + 2 * half] = pack_bf16(v[2] - h10, v[3] - h11);
            }
        }

        // ---- O += P V ----
#pragma unroll
        for (int np = 0; np < 4; np++) {       // dim-tile pairs (16 dims)
#pragma unroll
            for (int kc = 0; kc < 4; kc++) {   // key chunks of 16
                uint32_t vbh[4], vbl[4];
                int g = lane >> 3;
                int key = kc * 16 + (g & 1) * 8 + (lane & 7);
                int dim = np * 16 + (g >> 1) * 8;
                uint32_t ad = (uint32_t)((key * FSTR + dim) * 2);
                ldsm_x4_t(vbh, aVh + ad);
                ldsm_x4_t(vbl, aVl + ad);
                mma_bf16(oacc[2 * np],     pa_h[kc], vbh);
                mma_bf16(oacc[2 * np],     pa_l[kc], vbh);
                mma_bf16(oacc[2 * np],     pa_h[kc], vbl);
                mma_bf16(oacc[2 * np + 1], pa_h[kc], vbh + 2);
                mma_bf16(oacc[2 * np + 1], pa_l[kc], vbh + 2);
                mma_bf16(oacc[2 * np + 1], pa_h[kc], vbl + 2);
            }
        }
    }

    // ---- finalize & store as bf16 hi/lo ----
    const float i0 = 1.f / l0;
    const float i1 = 1.f / l1;
    const size_t ob0 = ((size_t)b * Sq + r0g) * Dq + h * DKq + 2 * (lane & 3);
#pragma unroll
    for (int nt = 0; nt < 8; nt++) {
        float x0 = oacc[nt][0] * i0, x1 = oacc[nt][1] * i0;
        float y0 = oacc[nt][2] * i1, y1 = oacc[nt][3] * i1;
        float hx0 = __bfloat162float(__float2bfloat16(x0));
        float hx1 = __bfloat162float(__float2bfloat16(x1));
        float hy0 = __bfloat162float(__float2bfloat16(y0));
        float hy1 = __bfloat162float(__float2bfloat16(y1));
        size_t o0 = ob0 + nt * 8;
        size_t o1 = o0 + 8 * (size_t)Dq;
        *(uint32_t*)(AOh + o0) = pack_bf16(hx0, hx1);
        *(uint32_t*)(AOl + o0) = pack_bf16(x0 - hx0, x1 - hx1);
        *(uint32_t*)(AOh + o1) = pack_bf16(hy0, hy1);
        *(uint32_t*)(AOl + o1) = pack_bf16(y0 - hy0, y1 - hy1);
    }
}

// ---------------------------------------------------------------------------
extern "C" void kernel_launch(void* const* d_in, const int* in_sizes, int n_in,
                              void* d_out, int out_size)
{
    const float* x    = (const float*)d_in[0];
    const float* W_Q  = (const float*)d_in[1];
    const float* W_K  = (const float*)d_in[2];
    const float* W_V  = (const float*)d_in[3];
    const float* W_O  = (const float*)d_in[4];
    const float* gain = (const float*)d_in[5];
    float* out = (float*)d_out;

    float *Qp, *Kp, *Vp, *sinp, *cosp;
    __nv_bfloat16 *xh, *xl, *aoh, *aol, *Wh, *Wl;
    __nv_bfloat16 *qh, *ql, *kh, *kl, *vh, *vl;
    cudaGetSymbolAddress((void**)&Qp,   g_Q);
    cudaGetSymbolAddress((void**)&Kp,   g_K);
    cudaGetSymbolAddress((void**)&Vp,   g_V);
    cudaGetSymbolAddress((void**)&sinp, g_sin);
    cudaGetSymbolAddress((void**)&cosp, g_cos);
    cudaGetSymbolAddress((void**)&xh,   g_xh);
    cudaGetSymbolAddress((void**)&xl,   g_xl);
    cudaGetSymbolAddress((void**)&aoh,  g_aoh);
    cudaGetSymbolAddress((void**)&aol,  g_aol);
    cudaGetSymbolAddress((void**)&Wh,   g_Wh);
    cudaGetSymbolAddress((void**)&Wl,   g_Wl);
    cudaGetSymbolAddress((void**)&qh,   g_Qh);
    cudaGetSymbolAddress((void**)&ql,   g_Ql);
    cudaGetSymbolAddress((void**)&kh,   g_Kh);
    cudaGetSymbolAddress((void**)&kl,   g_Kl);
    cudaGetSymbolAddress((void**)&vh,   g_Vh);
    cudaGetSymbolAddress((void**)&vl,   g_Vl);

    cudaFuncSetAttribute(gemm_tc,
                         cudaFuncAttributeMaxDynamicSharedMemorySize, GEMM_SMEM);
    cudaFuncSetAttribute(flash_tc,
                         cudaFuncAttributeMaxDynamicSharedMemorySize, FLASH_SMEM);

    const int nx4 = NR * Dq / 4;       // 1M float4
    const int nw4 = Dq * Dq / 4;       // 256K float4
    const size_t WSZ = (size_t)Dq * Dq;

    // splits + table
    split_kernel<<<nx4 / 256, 256>>>(x, xh, xl, nx4, 1.f);
    split_kernel<<<nw4 / 256, 256>>>(W_Q, Wh + 0*WSZ, Wl + 0*WSZ, nw4, 1.f);
    split_kernel<<<nw4 / 256, 256>>>(W_K, Wh + 1*WSZ, Wl + 1*WSZ, nw4, 1.f);
    split_kernel<<<nw4 / 256, 256>>>(W_V, Wh + 2*WSZ, Wl + 2*WSZ, nw4, 1.f);
    split_kernel<<<nw4 / 256, 256>>>(W_O, Wh + 3*WSZ, Wl + 3*WSZ, nw4, 1.f);
    rope_table_kernel<<<Sq * 32 / 256, 256>>>(sinp, cosp);

    // projections on tensor cores
    dim3 gg(Dq / 128, NR / 128);       // (8, 32)
    gemm_tc<<<gg, 256, GEMM_SMEM>>>(xh, xl, Wh + 0*WSZ, Wl + 0*WSZ, Qp, NR, Dq, Dq);
    gemm_tc<<<gg, 256, GEMM_SMEM>>>(xh, xl, Wh + 1*WSZ, Wl + 1*WSZ, Kp, NR, Dq, Dq);
    gemm_tc<<<gg, 256, GEMM_SMEM>>>(xh, xl, Wh + 2*WSZ, Wl + 2*WSZ, Vp, NR, Dq, Dq);

    norm_rope_kernel<<<NR, 256>>>(Qp, gain, sinp, cosp);
    norm_rope_kernel<<<NR, 256>>>(Kp, gain, sinp, cosp);

    // pre-split attention operands (1/8 folded into Q)
    split_kernel<<<nx4 / 256, 256>>>(Qp, qh, ql, nx4, 0.125f);
    split_kernel<<<nx4 / 256, 256>>>(Kp, kh, kl, nx4, 1.f);
    split_kernel<<<nx4 / 256, 256>>>(Vp, vh, vl, nx4, 1.f);

    // tensor-core flash attention -> bf16 hi/lo output
    flash_tc<<<dim3(Sq / 64, Hq, Bq), 128, FLASH_SMEM>>>(qh, ql, kh, kl, vh, vl, aoh, aol);

    gemm_tc<<<gg, 256, GEMM_SMEM>>>(aoh, aol, Wh + 3*WSZ, Wl + 3*WSZ, out, NR, Dq, Dq);
}